// round 13
// baseline (speedup 1.0000x reference)
#include <cuda_runtime.h>
#include <cuda_fp16.h>
#include <cstdint>

#define B_ 8
#define N_ 2048
#define D_ 128
#define NCK 32                // gemm1 k-chunks per CTA (split-K=2: 32 x 32 = 1024)
#define CK 32                 // k per chunk
#define SHALF (B_ * N_ * D_)
#define APITCH 136            // gemm1 A: halfs per k-row (128 j + pad) -> 272B
#define BPITCH1 40            // gemm1 B: halfs per d-row (32 k + pad) -> 80B
#define BPITCH 24             // gemm2 W,X: halfs per row (16 k + pad) -> 48B

// ---------------------------------------------------------------------------
// Device scratch (no runtime allocation allowed)
// ---------------------------------------------------------------------------
__device__ float  g_S[2 * SHALF];       // two split-K partial sums (64 MB)
__device__ int    g_deg[B_ * N_];       // nnz per cost row
__device__ __half g_Bth[B_ * D_ * N_];  // emb transposed fp16: Bth[b][d][i] (16 MB)

// ---------------------------------------------------------------------------
// helpers
// ---------------------------------------------------------------------------
__device__ __forceinline__ void hmma(float* c, const uint32_t* a, const uint32_t* b) {
    asm volatile(
        "mma.sync.aligned.m16n8k16.row.col.f32.f16.f16.f32 "
        "{%0,%1,%2,%3}, {%4,%5,%6,%7}, {%8,%9}, {%0,%1,%2,%3};"
        : "+f"(c[0]), "+f"(c[1]), "+f"(c[2]), "+f"(c[3])
        : "r"(a[0]), "r"(a[1]), "r"(a[2]), "r"(a[3]), "r"(b[0]), "r"(b[1]));
}
__device__ __forceinline__ void ldsm4(uint32_t* r, uint32_t addr) {
    asm volatile("ldmatrix.sync.aligned.m8n8.x4.shared.b16 {%0,%1,%2,%3}, [%4];"
                 : "=r"(r[0]), "=r"(r[1]), "=r"(r[2]), "=r"(r[3]) : "r"(addr));
}
__device__ __forceinline__ void ldsm4t(uint32_t* r, uint32_t addr) {
    asm volatile("ldmatrix.sync.aligned.m8n8.x4.trans.shared.b16 {%0,%1,%2,%3}, [%4];"
                 : "=r"(r[0]), "=r"(r[1]), "=r"(r[2]), "=r"(r[3]) : "r"(addr));
}
__device__ __forceinline__ uint32_t sm_addr(const void* p) {
    return (uint32_t)__cvta_generic_to_shared(p);
}
__device__ __forceinline__ void cp16(uint32_t dst, const void* src) {
    asm volatile("cp.async.ca.shared.global [%0], [%1], 16;"
                 :: "r"(dst), "l"(src) : "memory");
}
__device__ __forceinline__ void cp_commit() {
    asm volatile("cp.async.commit_group;" ::: "memory");
}
__device__ __forceinline__ void cp_wait_all() {
    asm volatile("cp.async.wait_group 0;" ::: "memory");
}
// exact fp32 -> fp16 hi/lo split of a float4, packed as half2 words
__device__ __forceinline__ void split_f4(float4 v, uint32_t& h0, uint32_t& h1,
                                         uint32_t& l0, uint32_t& l1) {
    __half2 a = __floats2half2_rn(v.x, v.y);
    __half2 b = __floats2half2_rn(v.z, v.w);
    float2 af = __half22float2(a), bf = __half22float2(b);
    __half2 c = __floats2half2_rn(v.x - af.x, v.y - af.y);
    __half2 d = __floats2half2_rn(v.z - bf.x, v.w - bf.y);
    h0 = *(uint32_t*)&a; h1 = *(uint32_t*)&b;
    l0 = *(uint32_t*)&c; l1 = *(uint32_t*)&d;
}
// fp32 float4 -> fp16 (single rounding), packed as 2 half2 words
__device__ __forceinline__ void cvt_f4(float4 v, uint32_t& h0, uint32_t& h1) {
    __half2 a = __floats2half2_rn(v.x, v.y);
    __half2 b = __floats2half2_rn(v.z, v.w);
    h0 = *(uint32_t*)&a; h1 = *(uint32_t*)&b;
}

// ---------------------------------------------------------------------------
// prep2 (fused): transpose emb[b][i][d] -> fp16 g_Bth[b][d][i], zero g_deg
// ---------------------------------------------------------------------------
__global__ void prep2_kernel(const float* __restrict__ emb) {
    __shared__ float tile[32][33];
    int b = blockIdx.z;
    int i0 = blockIdx.x * 32;
    int d0 = blockIdx.y * 32;
    int tx = threadIdx.x, ty = threadIdx.y;   // (32, 8)
    int lbid = blockIdx.x + gridDim.x * (blockIdx.y + gridDim.y * blockIdx.z);
    int gid = lbid * 256 + ty * 32 + tx;
    if (gid < B_ * N_) g_deg[gid] = 0;

    const float* eB = emb + (size_t)b * N_ * D_;
    #pragma unroll
    for (int r = 0; r < 32; r += 8)
        tile[ty + r][tx] = eB[(size_t)(i0 + ty + r) * D_ + d0 + tx];
    __syncthreads();
    #pragma unroll
    for (int r = 0; r < 32; r += 8) {
        size_t o = (size_t)b * D_ * N_ + (size_t)(d0 + ty + r) * N_ + i0 + tx;
        g_Bth[o] = __float2half_rn(tile[tx][ty + r]);
    }
}

// ---------------------------------------------------------------------------
// gemm1 on mma.sync, single-term fp16 x fp16, split-K=2, CK=32 chunks.
// C[j][d] += cost[k][j0+j] * Bth[d][k] over this CTA's K half (1024).
// CTA tile 128j x 128d, grid (16, 8, 2) = 256 CTAs -> 2 CTAs/SM.
// B tile loaded via cp.async (fp16 in gmem, no register round-trip);
// A (cost) LDG held across the MMA section, cvt+STS after it.
// Per warp-chunk: 32 HMMA, 12 LDSM, 1 barrier.
// ---------------------------------------------------------------------------
__global__ __launch_bounds__(256, 2) void gemm1_mma_kernel(const float* __restrict__ cost)
{
    __shared__ __align__(16) __half sA[2][CK * APITCH];    // [stage][k][j]
    __shared__ __align__(16) __half sB[2][128 * BPITCH1];  // [stage][d][k]

    const int tid = threadIdx.x, lane = tid & 31, w = tid >> 5;
    const int b = blockIdx.y, j0 = blockIdx.x * 128;
    const int kz = blockIdx.z, kbase = kz * (N_ / 2);
    const float* cB = cost + (size_t)b * N_ * N_;
    const __half* bT = g_Bth + (size_t)b * D_ * N_;

    // load-role indices
    const int kkA = w;                 // warp loads cost rows kkA + 8q, q=0..3
    const int jq  = lane;
    const int dB  = tid >> 1;          // B row (0..127)
    const int kqB = (tid & 1) * 16;    // 16-half (32B) chunk -> 2 cp.async

    // mma-role indices: warp tile 32m x 64n
    const int wm = w & 3, wn = w >> 2;
    const int m0w = wm * 32, n0w = wn * 64;
    const int rsel = (lane & 7) + ((lane & 16) ? 8 : 0);
    const int csel = (lane & 8) ? 8 : 0;

    float acc[2][8][4];
    #pragma unroll
    for (int mi = 0; mi < 2; mi++)
        #pragma unroll
        for (int ni = 0; ni < 8; ni++)
            #pragma unroll
            for (int q = 0; q < 4; q++) acc[mi][ni][q] = 0.f;

    // ---- prologue: fill stage 0 with chunk 0 ----
    {
        const int i0 = kbase;
        // B via cp.async
        uint32_t bdst = sm_addr(&sB[0][dB * BPITCH1 + kqB]);
        cp16(bdst, bT + (size_t)dB * N_ + i0 + kqB);
        cp16(bdst + 16, bT + (size_t)dB * N_ + i0 + kqB + 8);
        cp_commit();
        // A via registers
        #pragma unroll
        for (int q = 0; q < 4; q++) {
            const int kr = kkA + 8 * q;
            float4 ca = *(const float4*)(cB + (size_t)(i0 + kr) * N_ + j0 + jq * 4);
            int cnt = (ca.x != 0.f) + (ca.y != 0.f) + (ca.z != 0.f) + (ca.w != 0.f);
            cnt = __reduce_add_sync(0xffffffffu, cnt);
            if (lane == q) atomicAdd(&g_deg[b * N_ + i0 + kr], cnt);
            uint32_t h0, h1;
            cvt_f4(ca, h0, h1);
            *(uint2*)&sA[0][kr * APITCH + jq * 4] = make_uint2(h0, h1);
        }
        cp_wait_all();
    }
    __syncthreads();

    // ---- main loop ----
    for (int c = 0; c < NCK; c++) {
        const int s = c & 1;
        const bool more = (c + 1 < NCK);
        const int ns = s ^ 1;

        // 1) issue next-chunk B cp.async + A prefetch LDGs (held regs)
        float4 ca[4];
        if (more) {
            const int i0 = kbase + (c + 1) * CK;
            uint32_t bdst = sm_addr(&sB[ns][dB * BPITCH1 + kqB]);
            cp16(bdst, bT + (size_t)dB * N_ + i0 + kqB);
            cp16(bdst + 16, bT + (size_t)dB * N_ + i0 + kqB + 8);
            cp_commit();
            #pragma unroll
            for (int q = 0; q < 4; q++)
                ca[q] = *(const float4*)(cB + (size_t)(i0 + kkA + 8 * q) * N_ + j0 + jq * 4);
        }

        // 2) consume stage s: 2 k-subchunks of 16; 12 LDSM, 32 HMMA
        #pragma unroll
        for (int ks = 0; ks < 2; ks++) {
            uint32_t ah[2][4], bh[4][4];
            #pragma unroll
            for (int mi = 0; mi < 2; mi++)
                ldsm4t(ah[mi], sm_addr(&sA[s][(ks * 16 + rsel) * APITCH + m0w + mi * 16 + csel]));
            #pragma unroll
            for (int nq = 0; nq < 4; nq++)
                ldsm4(bh[nq], sm_addr(&sB[s][(n0w + nq * 16 + rsel) * BPITCH1 + ks * 16 + csel]));
            #pragma unroll
            for (int mi = 0; mi < 2; mi++)
                #pragma unroll
                for (int ni = 0; ni < 8; ni++)
                    hmma(acc[mi][ni], ah[mi], &bh[ni >> 1][(ni & 1) * 2]);
        }

        // 3) degree + convert + store A chunk c+1, then drain B cp.async
        if (more) {
            const int i0 = kbase + (c + 1) * CK;
            #pragma unroll
            for (int q = 0; q < 4; q++) {
                const int kr = kkA + 8 * q;
                int cnt = (ca[q].x != 0.f) + (ca[q].y != 0.f) + (ca[q].z != 0.f) + (ca[q].w != 0.f);
                cnt = __reduce_add_sync(0xffffffffu, cnt);
                if (lane == q) atomicAdd(&g_deg[b * N_ + i0 + kr], cnt);
                uint32_t h0, h1;
                cvt_f4(ca[q], h0, h1);
                *(uint2*)&sA[ns][kr * APITCH + jq * 4] = make_uint2(h0, h1);
            }
            cp_wait_all();
        }
        __syncthreads();
    }

    // ---- epilogue: fragments -> g_S[kz][b][j][d] ----
    float* Sr = g_S + (size_t)kz * SHALF + ((size_t)(b * N_ + j0)) * D_;
    #pragma unroll
    for (int mi = 0; mi < 2; mi++) {
        int r = m0w + mi * 16 + (lane >> 2);
        #pragma unroll
        for (int ni = 0; ni < 8; ni++) {
            int cix = n0w + ni * 8 + 2 * (lane & 3);
            *(float2*)(Sr + (size_t)r * D_ + cix)       = make_float2(acc[mi][ni][0], acc[mi][ni][1]);
            *(float2*)(Sr + (size_t)(r + 8) * D_ + cix) = make_float2(acc[mi][ni][2], acc[mi][ni][3]);
        }
    }
}

// ---------------------------------------------------------------------------
// gemm2 on mma.sync fp16 hi/lo split (3 terms):
//   out[n,d] = relu( sum_f X[n,f] * W[d,f] + bias[d] )
//   X[n,f] = (f < 128) ? emb[n,f] : (S0[n,f-128]+S1[n,f-128]) / degree[n]
// CTA tile 64n x 128d, K = 256 in 16 chunks, grid 256, 256 threads.
// ---------------------------------------------------------------------------
__global__ __launch_bounds__(256, 2) void gemm2_mma_kernel(
    const float* __restrict__ emb, const float* __restrict__ W,
    const float* __restrict__ bias, float* __restrict__ out)
{
    __shared__ __align__(16) __half sX[2][2][64 * BPITCH];    // [stage][hi/lo][n][f]
    __shared__ __align__(16) __half sW[2][2][128 * BPITCH];   // [stage][hi/lo][d][f]

    const int tid = threadIdx.x, lane = tid & 31, w = tid >> 5;
    const int gn0 = blockIdx.x * 64;

    // producer roles
    const int nX = tid >> 2, fqX = (tid & 3) * 4;   // X: row nX, f-quad fqX
    const int dW = tid & 127, qW = tid >> 7;        // W: row dW, 8-f half qW
    const float invdeg = 1.0f / (float)g_deg[gn0 + nX];

    // mma roles: warp tile 16m x 64n; 4 m-slots x 2 n-slots
    const int wm = w & 3, wn = w >> 2;
    const int m0w = wm * 16, n0w = wn * 64;
    const int rA = lane & 15, cA = (lane & 16) ? 8 : 0;          // A row-major map
    const int rsel = (lane & 7) + ((lane & 16) ? 8 : 0);         // B map (proven)
    const int csel = (lane & 8) ? 8 : 0;

    float acc[8][4];
    #pragma unroll
    for (int ni = 0; ni < 8; ni++)
        #pragma unroll
        for (int q = 0; q < 4; q++) acc[ni][q] = 0.f;

    // bias preload (per-thread columns)
    float2 bb[8];
    #pragma unroll
    for (int ni = 0; ni < 8; ni++) {
        int cix = n0w + ni * 8 + 2 * (lane & 3);
        bb[ni] = make_float2(bias[cix], bias[cix + 1]);
    }

    // producer: fill stage st with f-chunk k0
    auto fill = [&](int k0, int st) {
        float4 xv;
        if (k0 < D_) {
            xv = *(const float4*)(emb + (size_t)(gn0 + nX) * D_ + k0 + fqX);
        } else {
            const float* s0p = g_S + (size_t)(gn0 + nX) * D_ + (k0 - D_) + fqX;
            float4 a = *(const float4*)s0p;
            float4 bq = *(const float4*)(s0p + SHALF);
            xv = make_float4((a.x + bq.x) * invdeg, (a.y + bq.y) * invdeg,
                             (a.z + bq.z) * invdeg, (a.w + bq.w) * invdeg);
        }
        float4 wv0 = *(const float4*)(W + (size_t)dW * 256 + k0 + qW * 8);
        float4 wv1 = *(const float4*)(W + (size_t)dW * 256 + k0 + qW * 8 + 4);

        uint32_t h0, h1, l0, l1;
        split_f4(xv, h0, h1, l0, l1);
        *(uint2*)&sX[st][0][nX * BPITCH + fqX] = make_uint2(h0, h1);
        *(uint2*)&sX[st][1][nX * BPITCH + fqX] = make_uint2(l0, l1);
        split_f4(wv0, h0, h1, l0, l1);
        *(uint2*)&sW[st][0][dW * BPITCH + qW * 8] = make_uint2(h0, h1);
        *(uint2*)&sW[st][1][dW * BPITCH + qW * 8] = make_uint2(l0, l1);
        split_f4(wv1, h0, h1, l0, l1);
        *(uint2*)&sW[st][0][dW * BPITCH + qW * 8 + 4] = make_uint2(h0, h1);
        *(uint2*)&sW[st][1][dW * BPITCH + qW * 8 + 4] = make_uint2(l0, l1);
    };

    fill(0, 0);
    __syncthreads();

    for (int c = 0; c < 16; c++) {
        const int s = c & 1;
        if (c + 1 < 16) fill((c + 1) * 16, s ^ 1);

        uint32_t ah[4], al[4], bh[4][4], bl[4][4];
        ldsm4(ah, sm_addr(&sX[s][0][(m0w + rA) * BPITCH + cA]));
        ldsm4(al, sm_addr(&sX[s][1][(m0w + rA) * BPITCH + cA]));
        #pragma unroll
        for (int nq = 0; nq < 4; nq++) {
            ldsm4(bh[nq], sm_addr(&sW[s][0][(n0w + nq * 16 + rsel) * BPITCH + csel]));
            ldsm4(bl[nq], sm_addr(&sW[s][1][(n0w + nq * 16 + rsel) * BPITCH + csel]));
        }
        #pragma unroll
        for (int ni = 0; ni < 8; ni++) {
            const uint32_t* BH = &bh[ni >> 1][(ni & 1) * 2];
            const uint32_t* BL = &bl[ni >> 1][(ni & 1) * 2];
            hmma(acc[ni], ah, BH);
            hmma(acc[ni], ah, BL);
            hmma(acc[ni], al, BH);
        }
        __syncthreads();
    }

    // epilogue: bias + relu + store
    const int r = m0w + (lane >> 2);
    #pragma unroll
    for (int ni = 0; ni < 8; ni++) {
        int cix = n0w + ni * 8 + 2 * (lane & 3);
        float* O0 = out + (size_t)(gn0 + r) * D_ + cix;
        float* O1 = out + (size_t)(gn0 + r + 8) * D_ + cix;
        *(float2*)O0 = make_float2(fmaxf(acc[ni][0] + bb[ni].x, 0.f),
                                   fmaxf(acc[ni][1] + bb[ni].y, 0.f));
        *(float2*)O1 = make_float2(fmaxf(acc[ni][2] + bb[ni].x, 0.f),
                                   fmaxf(acc[ni][3] + bb[ni].y, 0.f));
    }
}

// ---------------------------------------------------------------------------
extern "C" void kernel_launch(void* const* d_in, const int* in_sizes, int n_in,
                              void* d_out, int out_size)
{
    const float *emb = nullptr, *cost = nullptr, *W = nullptr, *bias = nullptr;
    for (int i = 0; i < n_in; i++) {
        int s = in_sizes[i];
        if      (s == B_ * N_ * N_) cost = (const float*)d_in[i];
        else if (s == B_ * N_ * D_) emb  = (const float*)d_in[i];
        else if (s == 2 * D_ * D_)  W    = (const float*)d_in[i];
        else if (s == D_)           bias = (const float*)d_in[i];
    }

    prep2_kernel<<<dim3(N_ / 32, D_ / 32, B_), dim3(32, 8)>>>(emb);
    gemm1_mma_kernel<<<dim3(16, 8, 2), 256>>>(cost);
    gemm2_mma_kernel<<<256, 256>>>(emb, W, bias, (float*)d_out);
}

// round 14
// speedup vs baseline: 1.2400x; 1.2400x over previous
#include <cuda_runtime.h>
#include <cuda_fp16.h>
#include <cstdint>

#define B_ 8
#define N_ 2048
#define D_ 128
#define NCK 64                // gemm1 k-chunks per CTA (split-K=2: 64 x 16 = 1024)
#define SHALF (B_ * N_ * D_)
#define APITCH 136            // gemm1 A: halfs per k-row (128 j + pad) -> 272B
#define BPITCH 24             // gemm1 B / gemm2 W,X: halfs per row (16 k + pad) -> 48B

// ---------------------------------------------------------------------------
// Device scratch (no runtime allocation allowed)
// ---------------------------------------------------------------------------
__device__ float  g_S[2 * SHALF];       // two split-K partial sums (64 MB)
__device__ int    g_deg[B_ * N_];       // nnz per cost row
__device__ __half g_Bth[B_ * D_ * N_];  // emb transposed fp16: Bth[b][d][i] (16 MB)

// ---------------------------------------------------------------------------
// helpers
// ---------------------------------------------------------------------------
__device__ __forceinline__ void hmma(float* c, const uint32_t* a, const uint32_t* b) {
    asm volatile(
        "mma.sync.aligned.m16n8k16.row.col.f32.f16.f16.f32 "
        "{%0,%1,%2,%3}, {%4,%5,%6,%7}, {%8,%9}, {%0,%1,%2,%3};"
        : "+f"(c[0]), "+f"(c[1]), "+f"(c[2]), "+f"(c[3])
        : "r"(a[0]), "r"(a[1]), "r"(a[2]), "r"(a[3]), "r"(b[0]), "r"(b[1]));
}
__device__ __forceinline__ void ldsm4(uint32_t* r, uint32_t addr) {
    asm volatile("ldmatrix.sync.aligned.m8n8.x4.shared.b16 {%0,%1,%2,%3}, [%4];"
                 : "=r"(r[0]), "=r"(r[1]), "=r"(r[2]), "=r"(r[3]) : "r"(addr));
}
__device__ __forceinline__ void ldsm4t(uint32_t* r, uint32_t addr) {
    asm volatile("ldmatrix.sync.aligned.m8n8.x4.trans.shared.b16 {%0,%1,%2,%3}, [%4];"
                 : "=r"(r[0]), "=r"(r[1]), "=r"(r[2]), "=r"(r[3]) : "r"(addr));
}
__device__ __forceinline__ uint32_t sm_addr(const void* p) {
    return (uint32_t)__cvta_generic_to_shared(p);
}
// exact fp32 -> fp16 hi/lo split of a float4, packed as half2 words
__device__ __forceinline__ void split_f4(float4 v, uint32_t& h0, uint32_t& h1,
                                         uint32_t& l0, uint32_t& l1) {
    __half2 a = __floats2half2_rn(v.x, v.y);
    __half2 b = __floats2half2_rn(v.z, v.w);
    float2 af = __half22float2(a), bf = __half22float2(b);
    __half2 c = __floats2half2_rn(v.x - af.x, v.y - af.y);
    __half2 d = __floats2half2_rn(v.z - bf.x, v.w - bf.y);
    h0 = *(uint32_t*)&a; h1 = *(uint32_t*)&b;
    l0 = *(uint32_t*)&c; l1 = *(uint32_t*)&d;
}
// fp32 float4 -> fp16 (single rounding), packed as 2 half2 words
__device__ __forceinline__ void cvt_f4(float4 v, uint32_t& h0, uint32_t& h1) {
    __half2 a = __floats2half2_rn(v.x, v.y);
    __half2 b = __floats2half2_rn(v.z, v.w);
    h0 = *(uint32_t*)&a; h1 = *(uint32_t*)&b;
}

// ---------------------------------------------------------------------------
// prep2 (fused): transpose emb[b][i][d] -> fp16 g_Bth[b][d][i], zero g_deg
// ---------------------------------------------------------------------------
__global__ void prep2_kernel(const float* __restrict__ emb) {
    __shared__ float tile[32][33];
    int b = blockIdx.z;
    int i0 = blockIdx.x * 32;
    int d0 = blockIdx.y * 32;
    int tx = threadIdx.x, ty = threadIdx.y;   // (32, 8)
    int lbid = blockIdx.x + gridDim.x * (blockIdx.y + gridDim.y * blockIdx.z);
    int gid = lbid * 256 + ty * 32 + tx;
    if (gid < B_ * N_) g_deg[gid] = 0;

    const float* eB = emb + (size_t)b * N_ * D_;
    #pragma unroll
    for (int r = 0; r < 32; r += 8)
        tile[ty + r][tx] = eB[(size_t)(i0 + ty + r) * D_ + d0 + tx];
    __syncthreads();
    #pragma unroll
    for (int r = 0; r < 32; r += 8) {
        size_t o = (size_t)b * D_ * N_ + (size_t)(d0 + ty + r) * N_ + i0 + tx;
        g_Bth[o] = __float2half_rn(tile[tx][ty + r]);
    }
}

// ---------------------------------------------------------------------------
// gemm1 on mma.sync, single-term fp16 x fp16, split-K=2 (structure = R11).
// C[j][d] += cost[k][j0+j] * Bth[d][k] over this CTA's K half (1024).
// CTA tile 128j x 128d, chunk 16, grid (16, 8, 2) = 256 CTAs -> 2 CTAs/SM.
// Distance-2 schedule (zero extra registers): at iter c the body is
//   1. STS chunk c+1 (regs loaded at iter c-1) into stage s^1   (drained at
//      the barrier ending iter c-1, so writable now)
//   2. LDG chunk c+2 into the SAME register set (one-iteration live range)
//   3. LDSM+MMA on stage s
//   4. barrier
// => each LDG has a full iteration (~2300 cyc) to land instead of only the
//    MMA section (~500 cyc): the exposed DRAM stall before STS disappears.
// ---------------------------------------------------------------------------
__global__ __launch_bounds__(256, 2) void gemm1_mma_kernel(const float* __restrict__ cost)
{
    __shared__ __align__(16) __half sA[2][16 * APITCH];   // [stage][k][j]
    __shared__ __align__(16) __half sB[2][128 * BPITCH];  // [stage][d][k]

    const int tid = threadIdx.x, lane = tid & 31, w = tid >> 5;
    const int b = blockIdx.y, j0 = blockIdx.x * 128;
    const int kz = blockIdx.z, kbase = kz * (N_ / 2);
    const float* cB = cost + (size_t)b * N_ * N_;
    const __half* bT = g_Bth + (size_t)b * D_ * N_;

    // load-role indices
    const int kkA = w;                 // this warp loads cost rows kkA, kkA+8
    const int jq  = lane;
    const int dB  = tid >> 1;          // B row (0..127)
    const int kqB = (tid & 1) * 8;     // 8-half chunk within k16 (uint4)

    // mma-role indices: warp tile 32m x 64n
    const int wm = w & 3, wn = w >> 2;
    const int m0w = wm * 32, n0w = wn * 64;
    const int rsel = (lane & 7) + ((lane & 16) ? 8 : 0);
    const int csel = (lane & 8) ? 8 : 0;

    float acc[2][8][4];
    #pragma unroll
    for (int mi = 0; mi < 2; mi++)
        #pragma unroll
        for (int ni = 0; ni < 8; ni++)
            #pragma unroll
            for (int q = 0; q < 4; q++) acc[mi][ni][q] = 0.f;

    // store chunk (held in ca0/ca1/ebv) into stage st, base k-index i0
    // (degree counted here: each chunk passes through exactly once)
    float4 ca0, ca1; uint4 ebv;
    auto store_chunk = [&](int i0, int st) {
        int c0 = (ca0.x != 0.f) + (ca0.y != 0.f) + (ca0.z != 0.f) + (ca0.w != 0.f);
        int c1 = (ca1.x != 0.f) + (ca1.y != 0.f) + (ca1.z != 0.f) + (ca1.w != 0.f);
        c0 = __reduce_add_sync(0xffffffffu, c0);
        c1 = __reduce_add_sync(0xffffffffu, c1);
        if (lane == 0) atomicAdd(&g_deg[b * N_ + i0 + kkA], c0);
        if (lane == 1) atomicAdd(&g_deg[b * N_ + i0 + kkA + 8], c1);
        uint32_t h0, h1;
        cvt_f4(ca0, h0, h1);
        *(uint2*)&sA[st][kkA * APITCH + jq * 4] = make_uint2(h0, h1);
        cvt_f4(ca1, h0, h1);
        *(uint2*)&sA[st][(kkA + 8) * APITCH + jq * 4] = make_uint2(h0, h1);
        *(uint4*)&sB[st][dB * BPITCH + kqB] = ebv;
    };
    auto load_chunk = [&](int i0) {
        ca0 = *(const float4*)(cB + (size_t)(i0 + kkA) * N_ + j0 + jq * 4);
        ca1 = *(const float4*)(cB + (size_t)(i0 + kkA + 8) * N_ + j0 + jq * 4);
        ebv = *(const uint4*)(bT + (size_t)dB * N_ + i0 + kqB);
    };

    // ---- prologue: chunk 0 -> stage 0; chunk 1 -> held regs ----
    load_chunk(kbase);
    store_chunk(kbase, 0);
    load_chunk(kbase + 16);          // chunk 1, held across the barrier
    __syncthreads();

    // ---- main loop ----
    for (int c = 0; c < NCK; c++) {
        const int s = c & 1;

        // 1) STS chunk c+1 (held regs) into stage s^1
        if (c + 1 < NCK)
            store_chunk(kbase + (c + 1) * 16, s ^ 1);

        // 2) LDG chunk c+2 into the same register set
        if (c + 2 < NCK)
            load_chunk(kbase + (c + 2) * 16);

        // 3) consume stage s: 6 LDSM, 16 HMMA
        uint32_t ah[2][4], bh[4][4];
        #pragma unroll
        for (int mi = 0; mi < 2; mi++)
            ldsm4t(ah[mi], sm_addr(&sA[s][rsel * APITCH + m0w + mi * 16 + csel]));
        #pragma unroll
        for (int nq = 0; nq < 4; nq++)
            ldsm4(bh[nq], sm_addr(&sB[s][(n0w + nq * 16 + rsel) * BPITCH + csel]));
        #pragma unroll
        for (int mi = 0; mi < 2; mi++)
            #pragma unroll
            for (int ni = 0; ni < 8; ni++)
                hmma(acc[mi][ni], ah[mi], &bh[ni >> 1][(ni & 1) * 2]);

        // 4) barrier (orders this iter's STS for next iter's LDSM)
        __syncthreads();
    }

    // ---- epilogue: fragments -> g_S[kz][b][j][d] ----
    float* Sr = g_S + (size_t)kz * SHALF + ((size_t)(b * N_ + j0)) * D_;
    #pragma unroll
    for (int mi = 0; mi < 2; mi++) {
        int r = m0w + mi * 16 + (lane >> 2);
        #pragma unroll
        for (int ni = 0; ni < 8; ni++) {
            int cix = n0w + ni * 8 + 2 * (lane & 3);
            *(float2*)(Sr + (size_t)r * D_ + cix)       = make_float2(acc[mi][ni][0], acc[mi][ni][1]);
            *(float2*)(Sr + (size_t)(r + 8) * D_ + cix) = make_float2(acc[mi][ni][2], acc[mi][ni][3]);
        }
    }
}

// ---------------------------------------------------------------------------
// gemm2 on mma.sync fp16 hi/lo split (3 terms):
//   out[n,d] = relu( sum_f X[n,f] * W[d,f] + bias[d] )
//   X[n,f] = (f < 128) ? emb[n,f] : (S0[n,f-128]+S1[n,f-128]) / degree[n]
// CTA tile 64n x 128d, K = 256 in 16 chunks, grid 256, 256 threads.
// ---------------------------------------------------------------------------
__global__ __launch_bounds__(256, 2) void gemm2_mma_kernel(
    const float* __restrict__ emb, const float* __restrict__ W,
    const float* __restrict__ bias, float* __restrict__ out)
{
    __shared__ __align__(16) __half sX[2][2][64 * BPITCH];    // [stage][hi/lo][n][f]
    __shared__ __align__(16) __half sW[2][2][128 * BPITCH];   // [stage][hi/lo][d][f]

    const int tid = threadIdx.x, lane = tid & 31, w = tid >> 5;
    const int gn0 = blockIdx.x * 64;

    // producer roles
    const int nX = tid >> 2, fqX = (tid & 3) * 4;   // X: row nX, f-quad fqX
    const int dW = tid & 127, qW = tid >> 7;        // W: row dW, 8-f half qW
    const float invdeg = 1.0f / (float)g_deg[gn0 + nX];

    // mma roles: warp tile 16m x 64n; 4 m-slots x 2 n-slots
    const int wm = w & 3, wn = w >> 2;
    const int m0w = wm * 16, n0w = wn * 64;
    const int rA = lane & 15, cA = (lane & 16) ? 8 : 0;          // A row-major map
    const int rsel = (lane & 7) + ((lane & 16) ? 8 : 0);         // B map (proven)
    const int csel = (lane & 8) ? 8 : 0;

    float acc[8][4];
    #pragma unroll
    for (int ni = 0; ni < 8; ni++)
        #pragma unroll
        for (int q = 0; q < 4; q++) acc[ni][q] = 0.f;

    // bias preload (per-thread columns)
    float2 bb[8];
    #pragma unroll
    for (int ni = 0; ni < 8; ni++) {
        int cix = n0w + ni * 8 + 2 * (lane & 3);
        bb[ni] = make_float2(bias[cix], bias[cix + 1]);
    }

    // producer: fill stage st with f-chunk k0
    auto fill = [&](int k0, int st) {
        float4 xv;
        if (k0 < D_) {
            xv = *(const float4*)(emb + (size_t)(gn0 + nX) * D_ + k0 + fqX);
        } else {
            const float* s0p = g_S + (size_t)(gn0 + nX) * D_ + (k0 - D_) + fqX;
            float4 a = *(const float4*)s0p;
            float4 bq = *(const float4*)(s0p + SHALF);
            xv = make_float4((a.x + bq.x) * invdeg, (a.y + bq.y) * invdeg,
                             (a.z + bq.z) * invdeg, (a.w + bq.w) * invdeg);
        }
        float4 wv0 = *(const float4*)(W + (size_t)dW * 256 + k0 + qW * 8);
        float4 wv1 = *(const float4*)(W + (size_t)dW * 256 + k0 + qW * 8 + 4);

        uint32_t h0, h1, l0, l1;
        split_f4(xv, h0, h1, l0, l1);
        *(uint2*)&sX[st][0][nX * BPITCH + fqX] = make_uint2(h0, h1);
        *(uint2*)&sX[st][1][nX * BPITCH + fqX] = make_uint2(l0, l1);
        split_f4(wv0, h0, h1, l0, l1);
        *(uint2*)&sW[st][0][dW * BPITCH + qW * 8] = make_uint2(h0, h1);
        *(uint2*)&sW[st][1][dW * BPITCH + qW * 8] = make_uint2(l0, l1);
        split_f4(wv1, h0, h1, l0, l1);
        *(uint2*)&sW[st][0][dW * BPITCH + qW * 8 + 4] = make_uint2(h0, h1);
        *(uint2*)&sW[st][1][dW * BPITCH + qW * 8 + 4] = make_uint2(l0, l1);
    };

    fill(0, 0);
    __syncthreads();

    for (int c = 0; c < 16; c++) {
        const int s = c & 1;
        if (c + 1 < 16) fill((c + 1) * 16, s ^ 1);

        uint32_t ah[4], al[4], bh[4][4], bl[4][4];
        ldsm4(ah, sm_addr(&sX[s][0][(m0w + rA) * BPITCH + cA]));
        ldsm4(al, sm_addr(&sX[s][1][(m0w + rA) * BPITCH + cA]));
        #pragma unroll
        for (int nq = 0; nq < 4; nq++) {
            ldsm4(bh[nq], sm_addr(&sW[s][0][(n0w + nq * 16 + rsel) * BPITCH + csel]));
            ldsm4(bl[nq], sm_addr(&sW[s][1][(n0w + nq * 16 + rsel) * BPITCH + csel]));
        }
        #pragma unroll
        for (int ni = 0; ni < 8; ni++) {
            const uint32_t* BH = &bh[ni >> 1][(ni & 1) * 2];
            const uint32_t* BL = &bl[ni >> 1][(ni & 1) * 2];
            hmma(acc[ni], ah, BH);
            hmma(acc[ni], ah, BL);
            hmma(acc[ni], al, BH);
        }
        __syncthreads();
    }

    // epilogue: bias + relu + store
    const int r = m0w + (lane >> 2);
    #pragma unroll
    for (int ni = 0; ni < 8; ni++) {
        int cix = n0w + ni * 8 + 2 * (lane & 3);
        float* O0 = out + (size_t)(gn0 + r) * D_ + cix;
        float* O1 = out + (size_t)(gn0 + r + 8) * D_ + cix;
        *(float2*)O0 = make_float2(fmaxf(acc[ni][0] + bb[ni].x, 0.f),
                                   fmaxf(acc[ni][1] + bb[ni].y, 0.f));
        *(float2*)O1 = make_float2(fmaxf(acc[ni][2] + bb[ni].x, 0.f),
                                   fmaxf(acc[ni][3] + bb[ni].y, 0.f));
    }
}

// ---------------------------------------------------------------------------
extern "C" void kernel_launch(void* const* d_in, const int* in_sizes, int n_in,
                              void* d_out, int out_size)
{
    const float *emb = nullptr, *cost = nullptr, *W = nullptr, *bias = nullptr;
    for (int i = 0; i < n_in; i++) {
        int s = in_sizes[i];
        if      (s == B_ * N_ * N_) cost = (const float*)d_in[i];
        else if (s == B_ * N_ * D_) emb  = (const float*)d_in[i];
        else if (s == 2 * D_ * D_)  W    = (const float*)d_in[i];
        else if (s == D_)           bias = (const float*)d_in[i];
    }

    prep2_kernel<<<dim3(N_ / 32, D_ / 32, B_), dim3(32, 8)>>>(emb);
    gemm1_mma_kernel<<<dim3(16, 8, 2), 256>>>(cost);
    gemm2_mma_kernel<<<256, 256>>>(emb, W, bias, (float*)d_out);
}

// round 15
// speedup vs baseline: 1.4409x; 1.1620x over previous
#include <cuda_runtime.h>
#include <cuda_fp16.h>
#include <cstdint>

#define B_ 8
#define N_ 2048
#define D_ 128
#define CK 32                 // gemm1 k per chunk
#define NCK1 32               // gemm1 chunks per CTA (split-K=2: 32 x 32 = 1024)
#define SHALF (B_ * N_ * D_)
#define APITCH 136            // gemm1 A: halfs per k-row (128 j + pad) -> 272B
#define BPITCH1 40            // gemm1 B: halfs per d-row (32 k + pad) -> 80B
#define BPITCH 24             // gemm2 W,X: halfs per row (16 k + pad) -> 48B

// ---------------------------------------------------------------------------
// Device scratch (no runtime allocation allowed)
// ---------------------------------------------------------------------------
__device__ float  g_S[2 * SHALF];       // two split-K partial sums (64 MB)
__device__ int    g_deg[B_ * N_];       // nnz per cost row
__device__ __half g_Bth[B_ * D_ * N_];  // emb transposed fp16: Bth[b][d][i] (16 MB)

// ---------------------------------------------------------------------------
// helpers
// ---------------------------------------------------------------------------
__device__ __forceinline__ void hmma(float* c, const uint32_t* a, const uint32_t* b) {
    asm volatile(
        "mma.sync.aligned.m16n8k16.row.col.f32.f16.f16.f32 "
        "{%0,%1,%2,%3}, {%4,%5,%6,%7}, {%8,%9}, {%0,%1,%2,%3};"
        : "+f"(c[0]), "+f"(c[1]), "+f"(c[2]), "+f"(c[3])
        : "r"(a[0]), "r"(a[1]), "r"(a[2]), "r"(a[3]), "r"(b[0]), "r"(b[1]));
}
__device__ __forceinline__ void ldsm4(uint32_t* r, uint32_t addr) {
    asm volatile("ldmatrix.sync.aligned.m8n8.x4.shared.b16 {%0,%1,%2,%3}, [%4];"
                 : "=r"(r[0]), "=r"(r[1]), "=r"(r[2]), "=r"(r[3]) : "r"(addr));
}
__device__ __forceinline__ void ldsm4t(uint32_t* r, uint32_t addr) {
    asm volatile("ldmatrix.sync.aligned.m8n8.x4.trans.shared.b16 {%0,%1,%2,%3}, [%4];"
                 : "=r"(r[0]), "=r"(r[1]), "=r"(r[2]), "=r"(r[3]) : "r"(addr));
}
__device__ __forceinline__ uint32_t sm_addr(const void* p) {
    return (uint32_t)__cvta_generic_to_shared(p);
}
// exact fp32 -> fp16 hi/lo split of a float4, packed as half2 words
__device__ __forceinline__ void split_f4(float4 v, uint32_t& h0, uint32_t& h1,
                                         uint32_t& l0, uint32_t& l1) {
    __half2 a = __floats2half2_rn(v.x, v.y);
    __half2 b = __floats2half2_rn(v.z, v.w);
    float2 af = __half22float2(a), bf = __half22float2(b);
    __half2 c = __floats2half2_rn(v.x - af.x, v.y - af.y);
    __half2 d = __floats2half2_rn(v.z - bf.x, v.w - bf.y);
    h0 = *(uint32_t*)&a; h1 = *(uint32_t*)&b;
    l0 = *(uint32_t*)&c; l1 = *(uint32_t*)&d;
}
// fp32 float4 -> fp16 (single rounding), packed as 2 half2 words
__device__ __forceinline__ void cvt_f4(float4 v, uint32_t& h0, uint32_t& h1) {
    __half2 a = __floats2half2_rn(v.x, v.y);
    __half2 b = __floats2half2_rn(v.z, v.w);
    h0 = *(uint32_t*)&a; h1 = *(uint32_t*)&b;
}

// ---------------------------------------------------------------------------
// prep2 (fused): transpose emb[b][i][d] -> fp16 g_Bth[b][d][i], zero g_deg
// ---------------------------------------------------------------------------
__global__ void prep2_kernel(const float* __restrict__ emb) {
    __shared__ float tile[32][33];
    int b = blockIdx.z;
    int i0 = blockIdx.x * 32;
    int d0 = blockIdx.y * 32;
    int tx = threadIdx.x, ty = threadIdx.y;   // (32, 8)
    int lbid = blockIdx.x + gridDim.x * (blockIdx.y + gridDim.y * blockIdx.z);
    int gid = lbid * 256 + ty * 32 + tx;
    if (gid < B_ * N_) g_deg[gid] = 0;

    const float* eB = emb + (size_t)b * N_ * D_;
    #pragma unroll
    for (int r = 0; r < 32; r += 8)
        tile[ty + r][tx] = eB[(size_t)(i0 + ty + r) * D_ + d0 + tx];
    __syncthreads();
    #pragma unroll
    for (int r = 0; r < 32; r += 8) {
        size_t o = (size_t)b * D_ * N_ + (size_t)(d0 + ty + r) * N_ + i0 + tx;
        g_Bth[o] = __float2half_rn(tile[tx][ty + r]);
    }
}

// ---------------------------------------------------------------------------
// gemm1 on mma.sync, single-term fp16 x fp16, split-K=2, CK=32 chunks.
// C[j][d] += cost[k][j0+j] * Bth[d][k] over this CTA's K half (1024).
// CTA tile 128j x 128d, grid (16, 8, 2) = 256 CTAs -> 2 CTAs/SM.
// Distance-2 schedule (R13, proven): at iter c:
//   1. STS chunk c+1 (regs loaded at iter c-1) into stage s^1
//   2. LDG chunk c+2 into the same register set (one-iteration live range)
//   3. LDSM+MMA on stage s (2 k16 subchunks: 12 LDSM, 32 HMMA per warp)
//   4. barrier
// CK=32 halves the per-chunk fixed overhead (barrier, LDSM warm-up, loop)
// per MMA vs R13. Held regs: ca[4] (16) + eb[2] (8) = 24.
// ---------------------------------------------------------------------------
__global__ __launch_bounds__(256, 2) void gemm1_mma_kernel(const float* __restrict__ cost)
{
    __shared__ __align__(16) __half sA[2][CK * APITCH];    // [stage][k][j]
    __shared__ __align__(16) __half sB[2][128 * BPITCH1];  // [stage][d][k]

    const int tid = threadIdx.x, lane = tid & 31, w = tid >> 5;
    const int b = blockIdx.y, j0 = blockIdx.x * 128;
    const int kz = blockIdx.z, kbase = kz * (N_ / 2);
    const float* cB = cost + (size_t)b * N_ * N_;
    const __half* bT = g_Bth + (size_t)b * D_ * N_;

    // load-role indices
    const int kkA = w;                 // warp loads cost rows kkA + 8q, q=0..3
    const int jq  = lane;
    const int dB  = tid >> 1;          // B row (0..127)
    const int kqB = (tid & 1) * 16;    // 16-half slice -> 2 uint4

    // mma-role indices: warp tile 32m x 64n
    const int wm = w & 3, wn = w >> 2;
    const int m0w = wm * 32, n0w = wn * 64;
    const int rsel = (lane & 7) + ((lane & 16) ? 8 : 0);
    const int csel = (lane & 8) ? 8 : 0;

    float acc[2][8][4];
    #pragma unroll
    for (int mi = 0; mi < 2; mi++)
        #pragma unroll
        for (int ni = 0; ni < 8; ni++)
            #pragma unroll
            for (int q = 0; q < 4; q++) acc[mi][ni][q] = 0.f;

    // held chunk registers (one-iteration live range)
    float4 ca[4]; uint4 eb[2];
    auto load_chunk = [&](int i0) {
        #pragma unroll
        for (int q = 0; q < 4; q++)
            ca[q] = *(const float4*)(cB + (size_t)(i0 + kkA + 8 * q) * N_ + j0 + jq * 4);
        eb[0] = *(const uint4*)(bT + (size_t)dB * N_ + i0 + kqB);
        eb[1] = *(const uint4*)(bT + (size_t)dB * N_ + i0 + kqB + 8);
    };
    auto store_chunk = [&](int i0, int st) {
        #pragma unroll
        for (int q = 0; q < 4; q++) {
            const int kr = kkA + 8 * q;
            int cnt = (ca[q].x != 0.f) + (ca[q].y != 0.f) + (ca[q].z != 0.f) + (ca[q].w != 0.f);
            cnt = __reduce_add_sync(0xffffffffu, cnt);
            if (lane == q) atomicAdd(&g_deg[b * N_ + i0 + kr], cnt);
            uint32_t h0, h1;
            cvt_f4(ca[q], h0, h1);
            *(uint2*)&sA[st][kr * APITCH + jq * 4] = make_uint2(h0, h1);
        }
        *(uint4*)&sB[st][dB * BPITCH1 + kqB] = eb[0];
        *(uint4*)&sB[st][dB * BPITCH1 + kqB + 8] = eb[1];
    };

    // ---- prologue: chunk 0 -> stage 0; chunk 1 -> held regs ----
    load_chunk(kbase);
    store_chunk(kbase, 0);
    load_chunk(kbase + CK);
    __syncthreads();

    // ---- main loop ----
    for (int c = 0; c < NCK1; c++) {
        const int s = c & 1;

        // 1) STS chunk c+1 (held regs) into stage s^1
        if (c + 1 < NCK1)
            store_chunk(kbase + (c + 1) * CK, s ^ 1);

        // 2) LDG chunk c+2 into the same register set
        if (c + 2 < NCK1)
            load_chunk(kbase + (c + 2) * CK);

        // 3) consume stage s: 2 k16 subchunks; 12 LDSM, 32 HMMA per warp
        #pragma unroll
        for (int ks = 0; ks < 2; ks++) {
            uint32_t ah[2][4], bh[4][4];
            #pragma unroll
            for (int mi = 0; mi < 2; mi++)
                ldsm4t(ah[mi], sm_addr(&sA[s][(ks * 16 + rsel) * APITCH + m0w + mi * 16 + csel]));
            #pragma unroll
            for (int nq = 0; nq < 4; nq++)
                ldsm4(bh[nq], sm_addr(&sB[s][(n0w + nq * 16 + rsel) * BPITCH1 + ks * 16 + csel]));
            #pragma unroll
            for (int mi = 0; mi < 2; mi++)
                #pragma unroll
                for (int ni = 0; ni < 8; ni++)
                    hmma(acc[mi][ni], ah[mi], &bh[ni >> 1][(ni & 1) * 2]);
        }

        // 4) barrier
        __syncthreads();
    }

    // ---- epilogue: fragments -> g_S[kz][b][j][d] ----
    float* Sr = g_S + (size_t)kz * SHALF + ((size_t)(b * N_ + j0)) * D_;
    #pragma unroll
    for (int mi = 0; mi < 2; mi++) {
        int r = m0w + mi * 16 + (lane >> 2);
        #pragma unroll
        for (int ni = 0; ni < 8; ni++) {
            int cix = n0w + ni * 8 + 2 * (lane & 3);
            *(float2*)(Sr + (size_t)r * D_ + cix)       = make_float2(acc[mi][ni][0], acc[mi][ni][1]);
            *(float2*)(Sr + (size_t)(r + 8) * D_ + cix) = make_float2(acc[mi][ni][2], acc[mi][ni][3]);
        }
    }
}

// ---------------------------------------------------------------------------
// gemm2 on mma.sync fp16 hi/lo split (3 terms), distance-2 schedule:
//   out[n,d] = relu( sum_f X[n,f] * W[d,f] + bias[d] )
//   X[n,f] = (f < 128) ? emb[n,f] : (S0[n,f-128]+S1[n,f-128]) / degree[n]
// CTA tile 64n x 128d, K = 256 in 16 chunks, grid 256, 256 threads.
// Held regs: xv (4) + wv0/wv1 (8) = 12.
// ---------------------------------------------------------------------------
__global__ __launch_bounds__(256, 2) void gemm2_mma_kernel(
    const float* __restrict__ emb, const float* __restrict__ W,
    const float* __restrict__ bias, float* __restrict__ out)
{
    __shared__ __align__(16) __half sX[2][2][64 * BPITCH];    // [stage][hi/lo][n][f]
    __shared__ __align__(16) __half sW[2][2][128 * BPITCH];   // [stage][hi/lo][d][f]

    const int tid = threadIdx.x, lane = tid & 31, w = tid >> 5;
    const int gn0 = blockIdx.x * 64;

    // producer roles
    const int nX = tid >> 2, fqX = (tid & 3) * 4;   // X: row nX, f-quad fqX
    const int dW = tid & 127, qW = tid >> 7;        // W: row dW, 8-f half qW
    const float invdeg = 1.0f / (float)g_deg[gn0 + nX];

    // mma roles: warp tile 16m x 64n; 4 m-slots x 2 n-slots
    const int wm = w & 3, wn = w >> 2;
    const int m0w = wm * 16, n0w = wn * 64;
    const int rA = lane & 15, cA = (lane & 16) ? 8 : 0;          // A row-major map
    const int rsel = (lane & 7) + ((lane & 16) ? 8 : 0);         // B map (proven)
    const int csel = (lane & 8) ? 8 : 0;

    float acc[8][4];
    #pragma unroll
    for (int ni = 0; ni < 8; ni++)
        #pragma unroll
        for (int q = 0; q < 4; q++) acc[ni][q] = 0.f;

    // bias preload (per-thread columns)
    float2 bb[8];
    #pragma unroll
    for (int ni = 0; ni < 8; ni++) {
        int cix = n0w + ni * 8 + 2 * (lane & 3);
        bb[ni] = make_float2(bias[cix], bias[cix + 1]);
    }

    // held chunk registers
    float4 xv, wv0, wv1;
    auto load_c = [&](int k0) {
        if (k0 < D_) {
            xv = *(const float4*)(emb + (size_t)(gn0 + nX) * D_ + k0 + fqX);
        } else {
            const float* s0p = g_S + (size_t)(gn0 + nX) * D_ + (k0 - D_) + fqX;
            float4 a = *(const float4*)s0p;
            float4 bq = *(const float4*)(s0p + SHALF);
            xv = make_float4((a.x + bq.x) * invdeg, (a.y + bq.y) * invdeg,
                             (a.z + bq.z) * invdeg, (a.w + bq.w) * invdeg);
        }
        wv0 = *(const float4*)(W + (size_t)dW * 256 + k0 + qW * 8);
        wv1 = *(const float4*)(W + (size_t)dW * 256 + k0 + qW * 8 + 4);
    };
    auto store_c = [&](int st) {
        uint32_t h0, h1, l0, l1;
        split_f4(xv, h0, h1, l0, l1);
        *(uint2*)&sX[st][0][nX * BPITCH + fqX] = make_uint2(h0, h1);
        *(uint2*)&sX[st][1][nX * BPITCH + fqX] = make_uint2(l0, l1);
        split_f4(wv0, h0, h1, l0, l1);
        *(uint2*)&sW[st][0][dW * BPITCH + qW * 8] = make_uint2(h0, h1);
        *(uint2*)&sW[st][1][dW * BPITCH + qW * 8] = make_uint2(l0, l1);
        split_f4(wv1, h0, h1, l0, l1);
        *(uint2*)&sW[st][0][dW * BPITCH + qW * 8 + 4] = make_uint2(h0, h1);
        *(uint2*)&sW[st][1][dW * BPITCH + qW * 8 + 4] = make_uint2(l0, l1);
    };

    // ---- prologue ----
    load_c(0);
    store_c(0);
    load_c(16);
    __syncthreads();

    for (int c = 0; c < 16; c++) {
        const int s = c & 1;

        if (c + 1 < 16) store_c(s ^ 1);
        if (c + 2 < 16) load_c((c + 2) * 16);

        uint32_t ah[4], al[4], bh[4][4], bl[4][4];
        ldsm4(ah, sm_addr(&sX[s][0][(m0w + rA) * BPITCH + cA]));
        ldsm4(al, sm_addr(&sX[s][1][(m0w + rA) * BPITCH + cA]));
        #pragma unroll
        for (int nq = 0; nq < 4; nq++) {
            ldsm4(bh[nq], sm_addr(&sW[s][0][(n0w + nq * 16 + rsel) * BPITCH + csel]));
            ldsm4(bl[nq], sm_addr(&sW[s][1][(n0w + nq * 16 + rsel) * BPITCH + csel]));
        }
        #pragma unroll
        for (int ni = 0; ni < 8; ni++) {
            const uint32_t* BH = &bh[ni >> 1][(ni & 1) * 2];
            const uint32_t* BL = &bl[ni >> 1][(ni & 1) * 2];
            hmma(acc[ni], ah, BH);
            hmma(acc[ni], ah, BL);
            hmma(acc[ni], al, BH);
        }
        __syncthreads();
    }

    // epilogue: bias + relu + store
    const int r = m0w + (lane >> 2);
    #pragma unroll
    for (int ni = 0; ni < 8; ni++) {
        int cix = n0w + ni * 8 + 2 * (lane & 3);
        float* O0 = out + (size_t)(gn0 + r) * D_ + cix;
        float* O1 = out + (size_t)(gn0 + r + 8) * D_ + cix;
        *(float2*)O0 = make_float2(fmaxf(acc[ni][0] + bb[ni].x, 0.f),
                                   fmaxf(acc[ni][1] + bb[ni].y, 0.f));
        *(float2*)O1 = make_float2(fmaxf(acc[ni][2] + bb[ni].x, 0.f),
                                   fmaxf(acc[ni][3] + bb[ni].y, 0.f));
    }
}

// ---------------------------------------------------------------------------
extern "C" void kernel_launch(void* const* d_in, const int* in_sizes, int n_in,
                              void* d_out, int out_size)
{
    const float *emb = nullptr, *cost = nullptr, *W = nullptr, *bias = nullptr;
    for (int i = 0; i < n_in; i++) {
        int s = in_sizes[i];
        if      (s == B_ * N_ * N_) cost = (const float*)d_in[i];
        else if (s == B_ * N_ * D_) emb  = (const float*)d_in[i];
        else if (s == 2 * D_ * D_)  W    = (const float*)d_in[i];
        else if (s == D_)           bias = (const float*)d_in[i];
    }

    prep2_kernel<<<dim3(N_ / 32, D_ / 32, B_), dim3(32, 8)>>>(emb);
    gemm1_mma_kernel<<<dim3(16, 8, 2), 256>>>(cost);
    gemm2_mma_kernel<<<256, 256>>>(emb, W, bias, (float*)d_out);
}

// round 16
// speedup vs baseline: 1.4809x; 1.0278x over previous
#include <cuda_runtime.h>
#include <cuda_fp16.h>
#include <cstdint>

#define B_ 8
#define N_ 2048
#define D_ 128
#define CK 32                 // gemm1 k per chunk
#define NCK1 32               // gemm1 chunks per CTA (split-K=2: 32 x 32 = 1024)
#define SHALF (B_ * N_ * D_)
#define APITCH 136            // gemm1 A: halfs per k-row (128 j + pad) -> 272B
#define BPITCH1 40            // gemm1 B: halfs per d-row (32 k + pad) -> 80B
#define BPITCH 24             // gemm2 W,X: halfs per row (16 k + pad) -> 48B

// gemm1 dynamic smem layout: 4 stages of sA then 4 stages of sB
#define ASTAGE_BYTES (CK * APITCH * 2)        // 8704
#define BSTAGE_BYTES (128 * BPITCH1 * 2)      // 10240
#define G1_SMEM (4 * ASTAGE_BYTES + 4 * BSTAGE_BYTES)   // 75776

// ---------------------------------------------------------------------------
// Device scratch (no runtime allocation allowed)
// ---------------------------------------------------------------------------
__device__ float  g_S[2 * SHALF];       // two split-K partial sums (64 MB)
__device__ int    g_deg[B_ * N_];       // nnz per cost row
__device__ __half g_Bth[B_ * D_ * N_];  // emb transposed fp16: Bth[b][d][i] (16 MB)

// ---------------------------------------------------------------------------
// helpers
// ---------------------------------------------------------------------------
__device__ __forceinline__ void hmma(float* c, const uint32_t* a, const uint32_t* b) {
    asm volatile(
        "mma.sync.aligned.m16n8k16.row.col.f32.f16.f16.f32 "
        "{%0,%1,%2,%3}, {%4,%5,%6,%7}, {%8,%9}, {%0,%1,%2,%3};"
        : "+f"(c[0]), "+f"(c[1]), "+f"(c[2]), "+f"(c[3])
        : "r"(a[0]), "r"(a[1]), "r"(a[2]), "r"(a[3]), "r"(b[0]), "r"(b[1]));
}
__device__ __forceinline__ void ldsm4(uint32_t* r, uint32_t addr) {
    asm volatile("ldmatrix.sync.aligned.m8n8.x4.shared.b16 {%0,%1,%2,%3}, [%4];"
                 : "=r"(r[0]), "=r"(r[1]), "=r"(r[2]), "=r"(r[3]) : "r"(addr));
}
__device__ __forceinline__ void ldsm4t(uint32_t* r, uint32_t addr) {
    asm volatile("ldmatrix.sync.aligned.m8n8.x4.trans.shared.b16 {%0,%1,%2,%3}, [%4];"
                 : "=r"(r[0]), "=r"(r[1]), "=r"(r[2]), "=r"(r[3]) : "r"(addr));
}
__device__ __forceinline__ uint32_t sm_addr(const void* p) {
    return (uint32_t)__cvta_generic_to_shared(p);
}
// exact fp32 -> fp16 hi/lo split of a float4, packed as half2 words
__device__ __forceinline__ void split_f4(float4 v, uint32_t& h0, uint32_t& h1,
                                         uint32_t& l0, uint32_t& l1) {
    __half2 a = __floats2half2_rn(v.x, v.y);
    __half2 b = __floats2half2_rn(v.z, v.w);
    float2 af = __half22float2(a), bf = __half22float2(b);
    __half2 c = __floats2half2_rn(v.x - af.x, v.y - af.y);
    __half2 d = __floats2half2_rn(v.z - bf.x, v.w - bf.y);
    h0 = *(uint32_t*)&a; h1 = *(uint32_t*)&b;
    l0 = *(uint32_t*)&c; l1 = *(uint32_t*)&d;
}
// fp32 float4 -> fp16 (single rounding), packed as 2 half2 words
__device__ __forceinline__ void cvt_f4(float4 v, uint32_t& h0, uint32_t& h1) {
    __half2 a = __floats2half2_rn(v.x, v.y);
    __half2 b = __floats2half2_rn(v.z, v.w);
    h0 = *(uint32_t*)&a; h1 = *(uint32_t*)&b;
}

// ---------------------------------------------------------------------------
// prep2 (fused): transpose emb[b][i][d] -> fp16 g_Bth[b][d][i], zero g_deg
// ---------------------------------------------------------------------------
__global__ void prep2_kernel(const float* __restrict__ emb) {
    __shared__ float tile[32][33];
    int b = blockIdx.z;
    int i0 = blockIdx.x * 32;
    int d0 = blockIdx.y * 32;
    int tx = threadIdx.x, ty = threadIdx.y;   // (32, 8)
    int lbid = blockIdx.x + gridDim.x * (blockIdx.y + gridDim.y * blockIdx.z);
    int gid = lbid * 256 + ty * 32 + tx;
    if (gid < B_ * N_) g_deg[gid] = 0;

    const float* eB = emb + (size_t)b * N_ * D_;
    #pragma unroll
    for (int r = 0; r < 32; r += 8)
        tile[ty + r][tx] = eB[(size_t)(i0 + ty + r) * D_ + d0 + tx];
    __syncthreads();
    #pragma unroll
    for (int r = 0; r < 32; r += 8) {
        size_t o = (size_t)b * D_ * N_ + (size_t)(d0 + ty + r) * N_ + i0 + tx;
        g_Bth[o] = __float2half_rn(tile[tx][ty + r]);
    }
}

// ---------------------------------------------------------------------------
// gemm1 on mma.sync, single-term fp16 x fp16, split-K=2, CK=32 chunks.
// C[j][d] += cost[k][j0+j] * Bth[d][k] over this CTA's K half (1024).
// CTA tile 128j x 128d, grid (16, 8, 2) = 256 CTAs -> 2 CTAs/SM.
// 4-stage ring (dynamic smem, 75776 B), ONE barrier per TWO chunks:
//   pair (c, c+1):  store(c+2) -> load(c+3) -> MMA(c) ->
//                   store(c+3) -> load(c+4) -> MMA(c+1) -> barrier
// Stage (c+2)&3 / (c+3)&3 were consumed 2 / 1 pairs ago (before the last
// barrier), so the stores are race-free. 64 HMMA per warp between barriers
// halves the convoy + LDSM warm-up cost vs R14. Held regs: 24 (one set).
// ---------------------------------------------------------------------------
__global__ __launch_bounds__(256, 2) void gemm1_mma_kernel(const float* __restrict__ cost)
{
    extern __shared__ __align__(16) char smem_dyn[];

    const int tid = threadIdx.x, lane = tid & 31, w = tid >> 5;
    const int b = blockIdx.y, j0 = blockIdx.x * 128;
    const int kz = blockIdx.z, kbase = kz * (N_ / 2);
    const float* cB = cost + (size_t)b * N_ * N_;
    const __half* bT = g_Bth + (size_t)b * D_ * N_;

    // stage pointers
    auto sA_st = [&](int st) -> __half* {
        return (__half*)(smem_dyn + st * ASTAGE_BYTES);
    };
    auto sB_st = [&](int st) -> __half* {
        return (__half*)(smem_dyn + 4 * ASTAGE_BYTES + st * BSTAGE_BYTES);
    };

    // load-role indices
    const int kkA = w;                 // warp loads cost rows kkA + 8q, q=0..3
    const int jq  = lane;
    const int dB  = tid >> 1;          // B row (0..127)
    const int kqB = (tid & 1) * 16;    // 16-half slice -> 2 uint4

    // mma-role indices: warp tile 32m x 64n
    const int wm = w & 3, wn = w >> 2;
    const int m0w = wm * 32, n0w = wn * 64;
    const int rsel = (lane & 7) + ((lane & 16) ? 8 : 0);
    const int csel = (lane & 8) ? 8 : 0;

    float acc[2][8][4];
    #pragma unroll
    for (int mi = 0; mi < 2; mi++)
        #pragma unroll
        for (int ni = 0; ni < 8; ni++)
            #pragma unroll
            for (int q = 0; q < 4; q++) acc[mi][ni][q] = 0.f;

    // held chunk registers (single set, one-iteration live range)
    float4 ca[4]; uint4 eb[2];
    auto load_chunk = [&](int c) {
        const int i0 = kbase + c * CK;
        #pragma unroll
        for (int q = 0; q < 4; q++)
            ca[q] = *(const float4*)(cB + (size_t)(i0 + kkA + 8 * q) * N_ + j0 + jq * 4);
        eb[0] = *(const uint4*)(bT + (size_t)dB * N_ + i0 + kqB);
        eb[1] = *(const uint4*)(bT + (size_t)dB * N_ + i0 + kqB + 8);
    };
    auto store_chunk = [&](int c) {
        const int i0 = kbase + c * CK;
        const int st = c & 3;
        __half* sA = sA_st(st);
        __half* sB = sB_st(st);
        #pragma unroll
        for (int q = 0; q < 4; q++) {
            const int kr = kkA + 8 * q;
            int cnt = (ca[q].x != 0.f) + (ca[q].y != 0.f) + (ca[q].z != 0.f) + (ca[q].w != 0.f);
            cnt = __reduce_add_sync(0xffffffffu, cnt);
            if (lane == q) atomicAdd(&g_deg[b * N_ + i0 + kr], cnt);
            uint32_t h0, h1;
            cvt_f4(ca[q], h0, h1);
            *(uint2*)&sA[kr * APITCH + jq * 4] = make_uint2(h0, h1);
        }
        *(uint4*)&sB[dB * BPITCH1 + kqB] = eb[0];
        *(uint4*)&sB[dB * BPITCH1 + kqB + 8] = eb[1];
    };
    auto consume = [&](int c) {
        const int st = c & 3;
        __half* sA = sA_st(st);
        __half* sB = sB_st(st);
        #pragma unroll
        for (int ks = 0; ks < 2; ks++) {
            uint32_t ah[2][4], bh[4][4];
            #pragma unroll
            for (int mi = 0; mi < 2; mi++)
                ldsm4t(ah[mi], sm_addr(&sA[(ks * 16 + rsel) * APITCH + m0w + mi * 16 + csel]));
            #pragma unroll
            for (int nq = 0; nq < 4; nq++)
                ldsm4(bh[nq], sm_addr(&sB[(n0w + nq * 16 + rsel) * BPITCH1 + ks * 16 + csel]));
            #pragma unroll
            for (int mi = 0; mi < 2; mi++)
                #pragma unroll
                for (int ni = 0; ni < 8; ni++)
                    hmma(acc[mi][ni], ah[mi], &bh[ni >> 1][(ni & 1) * 2]);
        }
    };

    // ---- prologue: chunks 0,1 -> stages 0,1; chunk 2 -> held regs ----
    load_chunk(0);
    store_chunk(0);
    load_chunk(1);
    store_chunk(1);
    load_chunk(2);
    __syncthreads();

    // ---- main loop: one barrier per pair of chunks ----
    for (int p = 0; p < NCK1 / 2; p++) {
        const int c = 2 * p;

        if (c + 2 < NCK1) store_chunk(c + 2);
        if (c + 3 < NCK1) load_chunk(c + 3);
        consume(c);
        if (c + 3 < NCK1) store_chunk(c + 3);
        if (c + 4 < NCK1) load_chunk(c + 4);
        consume(c + 1);
        __syncthreads();
    }

    // ---- epilogue: fragments -> g_S[kz][b][j][d] ----
    float* Sr = g_S + (size_t)kz * SHALF + ((size_t)(b * N_ + j0)) * D_;
    #pragma unroll
    for (int mi = 0; mi < 2; mi++) {
        int r = m0w + mi * 16 + (lane >> 2);
        #pragma unroll
        for (int ni = 0; ni < 8; ni++) {
            int cix = n0w + ni * 8 + 2 * (lane & 3);
            *(float2*)(Sr + (size_t)r * D_ + cix)       = make_float2(acc[mi][ni][0], acc[mi][ni][1]);
            *(float2*)(Sr + (size_t)(r + 8) * D_ + cix) = make_float2(acc[mi][ni][2], acc[mi][ni][3]);
        }
    }
}

// ---------------------------------------------------------------------------
// gemm2 on mma.sync fp16 hi/lo split (3 terms), distance-2 schedule:
//   out[n,d] = relu( sum_f X[n,f] * W[d,f] + bias[d] )
//   X[n,f] = (f < 128) ? emb[n,f] : (S0[n,f-128]+S1[n,f-128]) / degree[n]
// CTA tile 64n x 128d, K = 256 in 16 chunks, grid 256, 256 threads.
// ---------------------------------------------------------------------------
__global__ __launch_bounds__(256, 2) void gemm2_mma_kernel(
    const float* __restrict__ emb, const float* __restrict__ W,
    const float* __restrict__ bias, float* __restrict__ out)
{
    __shared__ __align__(16) __half sX[2][2][64 * BPITCH];    // [stage][hi/lo][n][f]
    __shared__ __align__(16) __half sW[2][2][128 * BPITCH];   // [stage][hi/lo][d][f]

    const int tid = threadIdx.x, lane = tid & 31, w = tid >> 5;
    const int gn0 = blockIdx.x * 64;

    // producer roles
    const int nX = tid >> 2, fqX = (tid & 3) * 4;   // X: row nX, f-quad fqX
    const int dW = tid & 127, qW = tid >> 7;        // W: row dW, 8-f half qW
    const float invdeg = 1.0f / (float)g_deg[gn0 + nX];

    // mma roles: warp tile 16m x 64n; 4 m-slots x 2 n-slots
    const int wm = w & 3, wn = w >> 2;
    const int m0w = wm * 16, n0w = wn * 64;
    const int rA = lane & 15, cA = (lane & 16) ? 8 : 0;          // A row-major map
    const int rsel = (lane & 7) + ((lane & 16) ? 8 : 0);         // B map (proven)
    const int csel = (lane & 8) ? 8 : 0;

    float acc[8][4];
    #pragma unroll
    for (int ni = 0; ni < 8; ni++)
        #pragma unroll
        for (int q = 0; q < 4; q++) acc[ni][q] = 0.f;

    // bias preload (per-thread columns)
    float2 bb[8];
    #pragma unroll
    for (int ni = 0; ni < 8; ni++) {
        int cix = n0w + ni * 8 + 2 * (lane & 3);
        bb[ni] = make_float2(bias[cix], bias[cix + 1]);
    }

    // held chunk registers
    float4 xv, wv0, wv1;
    auto load_c = [&](int k0) {
        if (k0 < D_) {
            xv = *(const float4*)(emb + (size_t)(gn0 + nX) * D_ + k0 + fqX);
        } else {
            const float* s0p = g_S + (size_t)(gn0 + nX) * D_ + (k0 - D_) + fqX;
            float4 a = *(const float4*)s0p;
            float4 bq = *(const float4*)(s0p + SHALF);
            xv = make_float4((a.x + bq.x) * invdeg, (a.y + bq.y) * invdeg,
                             (a.z + bq.z) * invdeg, (a.w + bq.w) * invdeg);
        }
        wv0 = *(const float4*)(W + (size_t)dW * 256 + k0 + qW * 8);
        wv1 = *(const float4*)(W + (size_t)dW * 256 + k0 + qW * 8 + 4);
    };
    auto store_c = [&](int st) {
        uint32_t h0, h1, l0, l1;
        split_f4(xv, h0, h1, l0, l1);
        *(uint2*)&sX[st][0][nX * BPITCH + fqX] = make_uint2(h0, h1);
        *(uint2*)&sX[st][1][nX * BPITCH + fqX] = make_uint2(l0, l1);
        split_f4(wv0, h0, h1, l0, l1);
        *(uint2*)&sW[st][0][dW * BPITCH + qW * 8] = make_uint2(h0, h1);
        *(uint2*)&sW[st][1][dW * BPITCH + qW * 8] = make_uint2(l0, l1);
        split_f4(wv1, h0, h1, l0, l1);
        *(uint2*)&sW[st][0][dW * BPITCH + qW * 8 + 4] = make_uint2(h0, h1);
        *(uint2*)&sW[st][1][dW * BPITCH + qW * 8 + 4] = make_uint2(l0, l1);
    };

    // ---- prologue ----
    load_c(0);
    store_c(0);
    load_c(16);
    __syncthreads();

    for (int c = 0; c < 16; c++) {
        const int s = c & 1;

        if (c + 1 < 16) store_c(s ^ 1);
        if (c + 2 < 16) load_c((c + 2) * 16);

        uint32_t ah[4], al[4], bh[4][4], bl[4][4];
        ldsm4(ah, sm_addr(&sX[s][0][(m0w + rA) * BPITCH + cA]));
        ldsm4(al, sm_addr(&sX[s][1][(m0w + rA) * BPITCH + cA]));
        #pragma unroll
        for (int nq = 0; nq < 4; nq++) {
            ldsm4(bh[nq], sm_addr(&sW[s][0][(n0w + nq * 16 + rsel) * BPITCH + csel]));
            ldsm4(bl[nq], sm_addr(&sW[s][1][(n0w + nq * 16 + rsel) * BPITCH + csel]));
        }
        #pragma unroll
        for (int ni = 0; ni < 8; ni++) {
            const uint32_t* BH = &bh[ni >> 1][(ni & 1) * 2];
            const uint32_t* BL = &bl[ni >> 1][(ni & 1) * 2];
            hmma(acc[ni], ah, BH);
            hmma(acc[ni], ah, BL);
            hmma(acc[ni], al, BH);
        }
        __syncthreads();
    }

    // epilogue: bias + relu + store
    const int r = m0w + (lane >> 2);
    #pragma unroll
    for (int ni = 0; ni < 8; ni++) {
        int cix = n0w + ni * 8 + 2 * (lane & 3);
        float* O0 = out + (size_t)(gn0 + r) * D_ + cix;
        float* O1 = out + (size_t)(gn0 + r + 8) * D_ + cix;
        *(float2*)O0 = make_float2(fmaxf(acc[ni][0] + bb[ni].x, 0.f),
                                   fmaxf(acc[ni][1] + bb[ni].y, 0.f));
        *(float2*)O1 = make_float2(fmaxf(acc[ni][2] + bb[ni].x, 0.f),
                                   fmaxf(acc[ni][3] + bb[ni].y, 0.f));
    }
}

// ---------------------------------------------------------------------------
extern "C" void kernel_launch(void* const* d_in, const int* in_sizes, int n_in,
                              void* d_out, int out_size)
{
    const float *emb = nullptr, *cost = nullptr, *W = nullptr, *bias = nullptr;
    for (int i = 0; i < n_in; i++) {
        int s = in_sizes[i];
        if      (s == B_ * N_ * N_) cost = (const float*)d_in[i];
        else if (s == B_ * N_ * D_) emb  = (const float*)d_in[i];
        else if (s == 2 * D_ * D_)  W    = (const float*)d_in[i];
        else if (s == D_)           bias = (const float*)d_in[i];
    }

    static bool attr_set = false;
    if (!attr_set) {
        cudaFuncSetAttribute(gemm1_mma_kernel,
                             cudaFuncAttributeMaxDynamicSharedMemorySize, G1_SMEM);
        attr_set = true;
    }

    prep2_kernel<<<dim3(N_ / 32, D_ / 32, B_), dim3(32, 8)>>>(emb);
    gemm1_mma_kernel<<<dim3(16, 8, 2), 256, G1_SMEM>>>(cost);
    gemm2_mma_kernel<<<256, 256>>>(emb, W, bias, (float*)d_out);
}